// round 1
// baseline (speedup 1.0000x reference)
#include <cuda_runtime.h>
#include <math.h>
#include <stdint.h>

#define N_F 100000
#define N_H 49152
#define NE  400000
#define TT  12
#define HH  64
#define AHD 128

// ---------------- device scratch (static, allocation-free) ----------------
__device__ int   g_deg_se[N_F];
__device__ int   g_deg_de[N_H];
__device__ int   g_deg_sd[N_H];
__device__ int   g_deg_dd[N_F];
__device__ float g_agg[N_H * TT];
__device__ float g_hproc[(size_t)TT * N_H * HH];   // (t, n, h) layout, c_sd folded in
__device__ int   g_off[N_F + 1];
__device__ int   g_cur[N_F];
__device__ int   g_csr[NE];
__device__ float g_score1[TT * N_F];
__device__ float g_s1o[TT * N_F];
__device__ float g_att[2 * AHD + 2];               // u[128], c2[128], k1, k2

// ---------------- helpers ----------------
__device__ __forceinline__ float fast_tanh(float x) {
    float y;
    asm("tanh.approx.f32 %0, %1;" : "=f"(y) : "f"(x));
    return y;
}
__device__ __forceinline__ float nan0(float x) {
    x = (x == x) ? x : 0.f;
    return fminf(fmaxf(x, -3.402823466e38f), 3.402823466e38f);
}
__device__ __forceinline__ float lrelu(float x) { return x > 0.f ? x : 0.01f * x; }

// ---------------- kernels ----------------
__global__ void k_zero() {
    int i = blockIdx.x * blockDim.x + threadIdx.x;
    int stride = gridDim.x * blockDim.x;
    for (int j = i; j < N_F; j += stride) { g_deg_se[j] = 0; g_deg_dd[j] = 0; }
    for (int j = i; j < N_H; j += stride) { g_deg_de[j] = 0; g_deg_sd[j] = 0; }
    for (int j = i; j < N_H * TT; j += stride) g_agg[j] = 0.f;
}

__global__ void k_deg(const int* __restrict__ es, const int* __restrict__ ed,
                      const int* __restrict__ ds, const int* __restrict__ dd) {
    int e = blockIdx.x * blockDim.x + threadIdx.x;
    if (e >= NE) return;
    atomicAdd(&g_deg_se[es[e]], 1);
    atomicAdd(&g_deg_de[ed[e]], 1);
    atomicAdd(&g_deg_sd[ds[e]], 1);
    atomicAdd(&g_deg_dd[dd[e]], 1);
}

// encoder scatter: agg[d,t] += feat[s,t] * out_deg_enc[s]^-0.5
__global__ void k_enc(const float* __restrict__ feat, const int* __restrict__ es,
                      const int* __restrict__ ed) {
    int e = blockIdx.x * blockDim.x + threadIdx.x;
    if (e >= NE) return;
    int s = es[e], d = ed[e];
    float c = rsqrtf(fmaxf((float)g_deg_se[s], 1.f));
    const float4* fp = reinterpret_cast<const float4*>(feat + (size_t)s * 12);
    float4 v0 = fp[0], v1 = fp[1], v2 = fp[2];
    float vv[12] = {v0.x, v0.y, v0.z, v0.w, v1.x, v1.y, v1.z, v1.w, v2.x, v2.y, v2.z, v2.w};
    float* ap = g_agg + (size_t)d * TT;
#pragma unroll
    for (int t = 0; t < 12; t++) atomicAdd(ap + t, nan0(vv[t]) * c);
}

// h_enc + h_proc fused; c_sd folded into h_proc; layout (t=o, n, h)
__global__ void k_hproc(const float* __restrict__ Wenc, const float* __restrict__ benc,
                        const float* __restrict__ Wproc, const float* __restrict__ bproc) {
    __shared__ float sWe[TT * HH], sBe[TT * HH], sWp[TT * TT], sBp[TT];
    int tid = threadIdx.x;
    for (int i = tid; i < TT * HH; i += 256) { sWe[i] = Wenc[i]; sBe[i] = benc[i]; }
    if (tid < TT * TT) sWp[tid] = Wproc[tid];
    if (tid < TT) sBp[tid] = bproc[tid];
    __syncthreads();
    int n = blockIdx.x * 4 + (tid >> 6);
    int h = tid & 63;
    if (n >= N_H) return;
    float cde = rsqrtf(fmaxf((float)g_deg_de[n], 1.f));
    float csd = rsqrtf(fmaxf((float)g_deg_sd[n], 1.f));
    float he[TT];
#pragma unroll
    for (int t = 0; t < TT; t++) {
        float s = g_agg[n * TT + t] * cde;
        he[t] = lrelu(fmaf(s, sWe[t * HH + h], sBe[t * HH + h]));
    }
#pragma unroll
    for (int o = 0; o < TT; o++) {
        float v = sBp[o];
#pragma unroll
        for (int t = 0; t < TT; t++) v = fmaf(he[t], sWp[t * TT + o], v);
        v = fmaxf(v, 0.f) * csd;
        g_hproc[((size_t)o * N_H + n) * HH + h] = v;
    }
}

// exclusive prefix sum of in-deg(dec) -> g_off, and g_cur = exclusive offsets
__global__ void k_scanoff() {
    __shared__ int sh[1024];
    __shared__ int srun;
    int tid = threadIdx.x;
    if (tid == 0) { srun = 0; g_off[0] = 0; }
    __syncthreads();
    for (int base = 0; base < N_F; base += 1024) {
        int i = base + tid;
        int v = (i < N_F) ? g_deg_dd[i] : 0;
        sh[tid] = v;
        __syncthreads();
        for (int off = 1; off < 1024; off <<= 1) {
            int x = (tid >= off) ? sh[tid - off] : 0;
            __syncthreads();
            sh[tid] += x;
            __syncthreads();
        }
        int run = srun;
        if (i < N_F) { g_off[i + 1] = run + sh[tid]; g_cur[i] = run + sh[tid] - v; }
        __syncthreads();
        if (tid == 1023) srun = run + sh[1023];
        __syncthreads();
    }
}

__global__ void k_fill(const int* __restrict__ ds, const int* __restrict__ dd) {
    int e = blockIdx.x * blockDim.x + threadIdx.x;
    if (e >= NE) return;
    int pos = atomicAdd(&g_cur[dd[e]], 1);
    g_csr[pos] = ds[e];
}

// precompute u = W_lin@W_a1, c2 = b_lin@W_a1 + b_a1, k1 = W_lin.W_o, k2 = b_lin.W_o
__global__ void k_att(const float* __restrict__ Wlin, const float* __restrict__ blin,
                      const float* __restrict__ Wa1, const float* __restrict__ ba1,
                      const float* __restrict__ Wo) {
    int j = threadIdx.x;
    if (j < AHD) {
        float u = 0.f, c = 0.f;
        for (int h = 0; h < HH; h++) {
            float w = Wa1[h * AHD + j];
            u = fmaf(Wlin[h], w, u);
            c = fmaf(blin[h], w, c);
        }
        g_att[j] = u;
        g_att[AHD + j] = c + ba1[j];
    }
    if (j == 0) {
        float k1 = 0.f, k2 = 0.f;
        for (int h = 0; h < HH; h++) { k1 = fmaf(Wlin[h], Wo[h], k1); k2 = fmaf(blin[h], Wo[h], k2); }
        g_att[2 * AHD] = k1;
        g_att[2 * AHD + 1] = k2;
    }
}

// Heavy fused phase: per (64-row tile, t): gather a, space1 = leaky(a@W_t + b_t),
// score1 = tanh(space1@Wa1+ba1)@Wa2, s1o = space1@Wo.  Grid (ceil(N_F/64), 12), 256 thr.
__global__ void k_phase(const float* __restrict__ Wdec, const float* __restrict__ bdec,
                        const float* __restrict__ Wa1, const float* __restrict__ ba1,
                        const float* __restrict__ Wa2, const float* __restrict__ Wo) {
    __shared__ float sA[64][65];
    __shared__ float sW[64 * 64];
    __shared__ float sB[64];
    __shared__ float sBa1[128];
    __shared__ float sWa2[128];
    __shared__ float sWo[64];

    int t = blockIdx.y;
    int row0 = blockIdx.x * 64;
    int tid = threadIdx.x;

    for (int i = tid; i < 4096; i += 256) sW[i] = Wdec[t * 4096 + i];
    if (tid < 64) { sB[tid] = bdec[t * 64 + tid]; sWo[tid] = Wo[tid]; }
    if (tid < 128) { sBa1[tid] = ba1[tid]; sWa2[tid] = Wa2[tid]; }

    // gather (warp per row, 8 rows per warp); a premultiplied by c_dd
    int wid = tid >> 5, lane = tid & 31;
    for (int r = wid * 8; r < wid * 8 + 8; ++r) {
        int f = row0 + r;
        float a0 = 0.f, a1v = 0.f;
        if (f < N_F) {
            int beg = g_off[f], end = g_off[f + 1];
            for (int e = beg; e < end; e++) {
                const float* hp = g_hproc + ((size_t)t * N_H + g_csr[e]) * HH;
                a0 += hp[lane];
                a1v += hp[lane + 32];
            }
            float cdd = rsqrtf(fmaxf((float)g_deg_dd[f], 1.f));
            a0 *= cdd;
            a1v *= cdd;
        }
        sA[r][lane] = a0;
        sA[r][lane + 32] = a1v;
    }
    __syncthreads();

    int tf = tid >> 4, th = tid & 15;

    // GEMM1: 64x64 @ 64x64 (microtile 4x4 per thread)
    float acc[4][4];
#pragma unroll
    for (int i = 0; i < 4; i++)
#pragma unroll
        for (int j = 0; j < 4; j++) acc[i][j] = 0.f;
#pragma unroll 4
    for (int k = 0; k < 64; k++) {
        float av[4], bv[4];
#pragma unroll
        for (int i = 0; i < 4; i++) av[i] = sA[tf * 4 + i][k];
#pragma unroll
        for (int j = 0; j < 4; j++) bv[j] = sW[k * 64 + th * 4 + j];
#pragma unroll
        for (int i = 0; i < 4; i++)
#pragma unroll
            for (int j = 0; j < 4; j++) acc[i][j] = fmaf(av[i], bv[j], acc[i][j]);
    }
    __syncthreads();
    // space1 -> sA (bias + leaky)
#pragma unroll
    for (int i = 0; i < 4; i++)
#pragma unroll
        for (int j = 0; j < 4; j++)
            sA[tf * 4 + i][th * 4 + j] = lrelu(acc[i][j] + sB[th * 4 + j]);
    __syncthreads();

    // s1o = space1 @ Wo (one thread per row)
    if (tid < 64) {
        float v = 0.f;
#pragma unroll 8
        for (int k = 0; k < 64; k++) v = fmaf(sA[tid][k], sWo[k], v);
        int f = row0 + tid;
        if (f < N_F) g_s1o[t * N_F + f] = v;
    }

    // GEMM2 in two 64-wide halves of Wa1, accumulate score1 partials
    float sc[4] = {0.f, 0.f, 0.f, 0.f};
    for (int half = 0; half < 2; ++half) {
        __syncthreads();
        for (int i2 = tid; i2 < 4096; i2 += 256) {
            int k = i2 >> 6, jj = i2 & 63;
            sW[i2] = Wa1[k * 128 + half * 64 + jj];
        }
        __syncthreads();
        float z[4][4];
#pragma unroll
        for (int i = 0; i < 4; i++)
#pragma unroll
            for (int j = 0; j < 4; j++) z[i][j] = 0.f;
#pragma unroll 4
        for (int k = 0; k < 64; k++) {
            float av[4], bv[4];
#pragma unroll
            for (int i = 0; i < 4; i++) av[i] = sA[tf * 4 + i][k];
#pragma unroll
            for (int j = 0; j < 4; j++) bv[j] = sW[k * 64 + th * 4 + j];
#pragma unroll
            for (int i = 0; i < 4; i++)
#pragma unroll
                for (int j = 0; j < 4; j++) z[i][j] = fmaf(av[i], bv[j], z[i][j]);
        }
#pragma unroll
        for (int i = 0; i < 4; i++)
#pragma unroll
            for (int j = 0; j < 4; j++) {
                int jj = half * 64 + th * 4 + j;
                float tz = fast_tanh(z[i][j] + sBa1[jj]);
                sc[i] = fmaf(tz, sWa2[jj], sc[i]);
            }
    }
    // reduce over the 16 th-threads (b_a2 cancels in the 2-way softmax, omitted)
#pragma unroll
    for (int i = 0; i < 4; i++) {
        float v = sc[i];
        v += __shfl_down_sync(0xffffffffu, v, 8, 16);
        v += __shfl_down_sync(0xffffffffu, v, 4, 16);
        v += __shfl_down_sync(0xffffffffu, v, 2, 16);
        v += __shfl_down_sync(0xffffffffu, v, 1, 16);
        if (th == 0) {
            int f = row0 + tf * 4 + i;
            if (f < N_F) g_score1[t * N_F + f] = v;
        }
    }
}

// lightweight sequential scan step (scalar recurrence per node)
__global__ void k_step(const float* __restrict__ feat, const float* __restrict__ Wa2,
                       const float* __restrict__ bo, float* __restrict__ out, int t) {
    __shared__ float su[128], sc2[128], sw2[128];
    int tid = threadIdx.x;
    if (tid < 128) { su[tid] = g_att[tid]; sc2[tid] = g_att[128 + tid]; sw2[tid] = Wa2[tid]; }
    __syncthreads();
    int f = blockIdx.x * blockDim.x + tid;
    if (f >= N_F) return;
    float y = (t == 0) ? nan0(feat[(size_t)f * 12 + 11]) : out[(size_t)(t - 1) * N_F + f];
    float s2 = 0.f;
#pragma unroll 8
    for (int j = 0; j < 128; j++) s2 = fmaf(fast_tanh(fmaf(y, su[j], sc2[j])), sw2[j], s2);
    float s1 = g_score1[t * N_F + f];
    float mx = fmaxf(s1, s2);
    float e1 = __expf(s1 - mx), e2 = __expf(s2 - mx);
    float a1 = e1 / (e1 + e2);
    float s2o = fmaf(y, g_att[256], g_att[257]);
    out[(size_t)t * N_F + f] = fmaf(a1, g_s1o[t * N_F + f], (1.f - a1) * s2o) + bo[0];
}

// ---------------- launch ----------------
extern "C" void kernel_launch(void* const* d_in, const int* in_sizes, int n_in,
                              void* d_out, int out_size) {
    const float* feat  = (const float*)d_in[0];
    const int*   es    = (const int*)d_in[1];
    const int*   ed    = (const int*)d_in[2];
    const int*   ds    = (const int*)d_in[3];
    const int*   dd    = (const int*)d_in[4];
    const float* Wenc  = (const float*)d_in[5];
    const float* benc  = (const float*)d_in[6];
    const float* Wproc = (const float*)d_in[7];
    const float* bproc = (const float*)d_in[8];
    const float* Wdec  = (const float*)d_in[9];
    const float* bdec  = (const float*)d_in[10];
    const float* Wlin  = (const float*)d_in[11];
    const float* blin  = (const float*)d_in[12];
    const float* Wa1   = (const float*)d_in[13];
    const float* ba1   = (const float*)d_in[14];
    const float* Wa2   = (const float*)d_in[15];
    /* ba2 = d_in[16] cancels in 2-way softmax */
    const float* Wo    = (const float*)d_in[17];
    const float* bo    = (const float*)d_in[18];
    float* out = (float*)d_out;

    k_zero<<<512, 256>>>();
    k_deg<<<(NE + 255) / 256, 256>>>(es, ed, ds, dd);
    k_enc<<<(NE + 255) / 256, 256>>>(feat, es, ed);
    k_scanoff<<<1, 1024>>>();
    k_fill<<<(NE + 255) / 256, 256>>>(ds, dd);
    k_hproc<<<(N_H + 3) / 4, 256>>>(Wenc, benc, Wproc, bproc);
    k_att<<<1, 128>>>(Wlin, blin, Wa1, ba1, Wo);
    dim3 pg((N_F + 63) / 64, TT);
    k_phase<<<pg, 256>>>(Wdec, bdec, Wa1, ba1, Wa2, Wo);
    for (int t = 0; t < TT; t++)
        k_step<<<(N_F + 255) / 256, 256>>>(feat, Wa2, bo, out, t);
}